// round 5
// baseline (speedup 1.0000x reference)
#include <cuda_runtime.h>
#include <cuda_fp16.h>

#define N_NODES 100000
#define D 128
#define MT 256                                     // nodes per GEMM block
#define GEMM_SMEM_BYTES ((MT * D + D * D) * 4)     // As(128KB) + Ws(64KB) = 192KB

typedef unsigned long long u64;

// Scratch (allocation-free rule: __device__ globals)
__device__ int            g_row_ptr[N_NODES + 1];
__device__ float          g_agg[(size_t)N_NODES * D];
__device__ float          g_Wt[D * D];             // W transposed: [k][j]
__device__ unsigned short g_h16[(size_t)N_NODES * D];  // h in fp16

// ---- packed f32x2 helpers (sm_100+) ---------------------------------------
__device__ __forceinline__ u64 pack2(float x, float y) {
    u64 r; asm("mov.b64 %0, {%1, %2};" : "=l"(r) : "f"(x), "f"(y)); return r;
}
__device__ __forceinline__ u64 fma2(u64 a, u64 b, u64 c) {
    u64 d; asm("fma.rn.f32x2 %0, %1, %2, %3;" : "=l"(d) : "l"(a), "l"(b), "l"(c));
    return d;
}
__device__ __forceinline__ float2 unpack2(u64 v) {
    float2 f; asm("mov.b64 {%0, %1}, %2;" : "=f"(f.x), "=f"(f.y) : "l"(v)); return f;
}

union F4U { float4 f4; u64 u[2]; };

// ---------------------------------------------------------------------------
// Kernel 1: build CSR row pointers from sorted edge_rows (shfl for neighbor)
// ---------------------------------------------------------------------------
__global__ void build_row_ptr_kernel(const int* __restrict__ rows, int E) {
    int e    = blockIdx.x * blockDim.x + threadIdx.x;
    int lane = threadIdx.x & 31;
    int ee   = min(e, E - 1);
    int r    = rows[ee];
    int rp   = 0;
    if (lane == 0 && ee > 0) rp = rows[ee - 1];
    int rs = __shfl_up_sync(0xffffffff, r, 1);
    if (lane > 0) rp = rs;
    if (e >= E) return;
    if (e == 0) rp = -1;
    for (int j = rp + 1; j <= r; j++) g_row_ptr[j] = e;
    if (e == E - 1) {
        for (int j = r + 1; j <= N_NODES; j++) g_row_ptr[j] = E;
    }
}

// ---------------------------------------------------------------------------
// Kernel 2: transpose W -> g_Wt ([k][j])
// ---------------------------------------------------------------------------
__global__ void transpose_w_kernel(const float* __restrict__ W) {
    int j = blockIdx.x;
    int k = threadIdx.x;
    g_Wt[k * D + j] = W[j * D + k];
}

// ---------------------------------------------------------------------------
// Kernel 3: convert h (fp32) -> g_h16 (fp16), vectorized
// ---------------------------------------------------------------------------
__global__ void __launch_bounds__(256) convert_h_kernel(const float* __restrict__ h) {
    int i = blockIdx.x * blockDim.x + threadIdx.x;          // one float4 per thread
    const int total = (N_NODES * D) / 4;
    if (i >= total) return;
    float4 f = __ldg(((const float4*)h) + i);
    __half2 a = __floats2half2_rn(f.x, f.y);
    __half2 b = __floats2half2_rn(f.z, f.w);
    uint2 packed;
    packed.x = *(unsigned int*)&a;
    packed.y = *(unsigned int*)&b;
    ((uint2*)g_h16)[i] = packed;
}

// ---------------------------------------------------------------------------
// Kernel 4: SpMM on fp16 h — one warp per node.
// 16 lanes per edge, 2 edges per iteration; lane loads uint4 = 8 fp16 cols.
// Cross-group reduction (shfl_xor 16) at the end.
// ---------------------------------------------------------------------------
__global__ void __launch_bounds__(256) spmm_kernel(const int*   __restrict__ cols,
                                                   const float* __restrict__ vals) {
    int gwarp = (blockIdx.x * blockDim.x + threadIdx.x) >> 5;
    int lane  = threadIdx.x & 31;
    if (gwarp >= N_NODES) return;

    const int grp = lane >> 4;     // 0 / 1 : which edge of the pair
    const int sl  = lane & 15;     // 8-column group within the row

    int s = g_row_ptr[gwarp];
    int e = g_row_ptr[gwarp + 1];

    float acc[8];
    #pragma unroll
    for (int q = 0; q < 8; q++) acc[q] = 0.f;

    for (int base = s; base < e; base += 32) {
        int   idx = base + lane;
        int   c   = 0;
        float v   = 0.f;
        if (idx < e) {
            c = __ldg(&cols[idx]);     // coalesced metadata
            v = __ldg(&vals[idx]);
        }
        int cnt = min(32, e - base);

        if (cnt == 32) {
            #pragma unroll
            for (int j = 0; j < 32; j += 2) {
                int   src = j + grp;
                int   cc  = __shfl_sync(0xffffffff, c, src);
                float vv  = __shfl_sync(0xffffffff, v, src);
                uint4 hv  = __ldg((const uint4*)(g_h16 + (size_t)cc * D) + sl);
                const __half2* hp = (const __half2*)&hv;
                #pragma unroll
                for (int q = 0; q < 4; q++) {
                    float2 f = __half22float2(hp[q]);
                    acc[q * 2 + 0] += vv * f.x;
                    acc[q * 2 + 1] += vv * f.y;
                }
            }
        } else {
            for (int j = 0; j < cnt; j += 2) {
                int   src = min(j + grp, cnt - 1);
                int   cc  = __shfl_sync(0xffffffff, c, src);
                float vv  = __shfl_sync(0xffffffff, v, src);
                if (j + grp >= cnt) vv = 0.f;
                uint4 hv  = __ldg((const uint4*)(g_h16 + (size_t)cc * D) + sl);
                const __half2* hp = (const __half2*)&hv;
                #pragma unroll
                for (int q = 0; q < 4; q++) {
                    float2 f = __half22float2(hp[q]);
                    acc[q * 2 + 0] += vv * f.x;
                    acc[q * 2 + 1] += vv * f.y;
                }
            }
        }
    }

    // Combine the two edge-groups (each lane pair l, l^16 owns the same 8 cols).
    #pragma unroll
    for (int q = 0; q < 8; q++)
        acc[q] += __shfl_xor_sync(0xffffffff, acc[q], 16);

    if (grp == 0) {
        float* dst = g_agg + (size_t)gwarp * D + sl * 8;
        *(float4*)(dst)     = make_float4(acc[0], acc[1], acc[2], acc[3]);
        *(float4*)(dst + 4) = make_float4(acc[4], acc[5], acc[6], acc[7]);
    }
}

// ---------------------------------------------------------------------------
// Kernel 5: out = relu(agg @ W^T + b), f32x2 packed, 8x8 thread tile.
// 512 threads; block tile 256 nodes x 128 cols; thread: 8 nodes x 8 cols.
// ---------------------------------------------------------------------------
__global__ void __launch_bounds__(512, 1) gemm_bias_relu_kernel(const float* __restrict__ b,
                                                                float* __restrict__ out) {
    extern __shared__ float sm[];
    float* As = sm;             // [MT][D]  node-major
    float* Ws = sm + MT * D;    // [D][D]   k-major

    const int tid   = threadIdx.x;     // 0..511
    const int node0 = blockIdx.x * MT;
    const int tx    = tid & 15;        // 16 col groups (8 cols each)
    const int ty    = tid >> 4;        // 32 node groups (8 nodes each)

    // Load Wt (k-major) into shared — coalesced, conflict-free.
    for (int i = tid; i < (D * D) / 4; i += 512)
        ((float4*)Ws)[i] = ((const float4*)g_Wt)[i];

    // Load agg tile [MT][D], zero-pad out-of-range nodes.
    for (int i = tid; i < (MT * D) / 4; i += 512) {
        int n  = (i * 4) / D;
        int gn = node0 + n;
        float4 a4 = (gn < N_NODES)
                  ? ((const float4*)(g_agg + (size_t)gn * D))[(i * 4 % D) >> 2]
                  : make_float4(0.f, 0.f, 0.f, 0.f);
        ((float4*)As)[i] = a4;
    }
    __syncthreads();

    u64 acc[8][4];
    #pragma unroll
    for (int nn = 0; nn < 8; nn++)
        #pragma unroll
        for (int jp = 0; jp < 4; jp++)
            acc[nn][jp] = pack2(0.f, 0.f);

    for (int kk = 0; kk < D; kk += 4) {
        float4 a4[8];
        #pragma unroll
        for (int nn = 0; nn < 8; nn++)
            a4[nn] = *(const float4*)(As + (ty * 8 + nn) * D + kk);   // 2 distinct/warp

        #pragma unroll
        for (int t = 0; t < 4; t++) {
            const float* wr = Ws + (kk + t) * D;
            F4U wA, wB;
            wA.f4 = *(const float4*)(wr + tx * 4);
            wB.f4 = *(const float4*)(wr + 64 + tx * 4);
            #pragma unroll
            for (int nn = 0; nn < 8; nn++) {
                const float* ap = &a4[nn].x;
                u64 a2 = pack2(ap[t], ap[t]);
                acc[nn][0] = fma2(a2, wA.u[0], acc[nn][0]);
                acc[nn][1] = fma2(a2, wA.u[1], acc[nn][1]);
                acc[nn][2] = fma2(a2, wB.u[0], acc[nn][2]);
                acc[nn][3] = fma2(a2, wB.u[1], acc[nn][3]);
            }
        }
    }

    // Epilogue: + b, relu, two float4 stores per node.
    float4 bA = *(const float4*)(b + tx * 4);
    float4 bB = *(const float4*)(b + 64 + tx * 4);

    #pragma unroll
    for (int nn = 0; nn < 8; nn++) {
        int gn = node0 + ty * 8 + nn;
        if (gn < N_NODES) {
            float2 p0 = unpack2(acc[nn][0]);
            float2 p1 = unpack2(acc[nn][1]);
            float2 p2 = unpack2(acc[nn][2]);
            float2 p3 = unpack2(acc[nn][3]);
            float4 oA, oB;
            oA.x = fmaxf(p0.x + bA.x, 0.f);
            oA.y = fmaxf(p0.y + bA.y, 0.f);
            oA.z = fmaxf(p1.x + bA.z, 0.f);
            oA.w = fmaxf(p1.y + bA.w, 0.f);
            oB.x = fmaxf(p2.x + bB.x, 0.f);
            oB.y = fmaxf(p2.y + bB.y, 0.f);
            oB.z = fmaxf(p3.x + bB.z, 0.f);
            oB.w = fmaxf(p3.y + bB.w, 0.f);
            *(float4*)(out + (size_t)gn * D + tx * 4)      = oA;
            *(float4*)(out + (size_t)gn * D + 64 + tx * 4) = oB;
        }
    }
}

// ---------------------------------------------------------------------------
// Launch
// ---------------------------------------------------------------------------
extern "C" void kernel_launch(void* const* d_in, const int* in_sizes, int n_in,
                              void* d_out, int out_size) {
    const int*   edge_rows = (const int*)  d_in[0];
    const int*   edge_cols = (const int*)  d_in[1];
    const float* edge_vals = (const float*)d_in[2];
    const float* h         = (const float*)d_in[3];
    const float* W         = (const float*)d_in[4];
    const float* b         = (const float*)d_in[5];
    float*       out       = (float*)d_out;
    const int E = in_sizes[0];

    // 1) CSR row pointers
    build_row_ptr_kernel<<<(E + 255) / 256, 256>>>(edge_rows, E);

    // 2) W transpose (k-major)
    transpose_w_kernel<<<D, D>>>(W);

    // 3) h -> fp16
    {
        int total = (N_NODES * D) / 4;
        convert_h_kernel<<<(total + 255) / 256, 256>>>(h);
    }

    // 4) SpMM (fp16 gather, 2 edges/iter, fp32 accumulate)
    {
        long long total_threads = (long long)N_NODES * 32;
        int blocks = (int)((total_threads + 255) / 256);
        spmm_kernel<<<blocks, 256>>>(edge_cols, edge_vals);
    }

    // 5) GEMM + bias + relu (f32x2 packed, 8x8 tile)
    cudaFuncSetAttribute(gemm_bias_relu_kernel,
                         cudaFuncAttributeMaxDynamicSharedMemorySize,
                         GEMM_SMEM_BYTES);
    gemm_bias_relu_kernel<<<(N_NODES + MT - 1) / MT, 512, GEMM_SMEM_BYTES>>>(b, out);
}

// round 6
// speedup vs baseline: 1.0683x; 1.0683x over previous
#include <cuda_runtime.h>
#include <cuda_fp16.h>
#include <cstdint>

#define N_NODES 100000
#define D 128
#define MTG 128                                   // nodes per GEMM block
#define GEMM_SMEM_BYTES (32768 * 4)               // As_frag(64KB) + Ws_frag(64KB)

typedef unsigned long long u64;

// Scratch (allocation-free rule: __device__ globals)
__device__ int            g_row_ptr[N_NODES + 1];
__device__ float          g_agg[(size_t)N_NODES * D];
__device__ unsigned short g_h16[(size_t)N_NODES * D];  // h in fp16

// ---------------------------------------------------------------------------
// tf32 helpers
// ---------------------------------------------------------------------------
__device__ __forceinline__ uint32_t f2tf32(float f) {
    uint32_t r; asm("cvt.rna.tf32.f32 %0, %1;" : "=r"(r) : "f"(f)); return r;
}
__device__ __forceinline__ void mma_tf32(float d[4],
                                         uint32_t a0, uint32_t a1, uint32_t a2, uint32_t a3,
                                         uint32_t b0, uint32_t b1) {
    asm volatile(
        "mma.sync.aligned.m16n8k8.row.col.f32.tf32.tf32.f32 "
        "{%0,%1,%2,%3}, {%4,%5,%6,%7}, {%8,%9}, {%0,%1,%2,%3};"
        : "+f"(d[0]), "+f"(d[1]), "+f"(d[2]), "+f"(d[3])
        : "r"(a0), "r"(a1), "r"(a2), "r"(a3), "r"(b0), "r"(b1));
}
__device__ __forceinline__ void unpack_u64(u64 v, uint32_t& lo, uint32_t& hi) {
    asm("mov.b64 {%0, %1}, %2;" : "=r"(lo), "=r"(hi) : "l"(v));
}

// ---------------------------------------------------------------------------
// Kernel 1: prep — CSR row pointers (sorted rows, shfl neighbor) AND h->fp16.
// Both workloads are ~3.2M items; same grid covers both.
// ---------------------------------------------------------------------------
__global__ void __launch_bounds__(256) prep_kernel(const int* __restrict__ rows, int E,
                                                   const float* __restrict__ h) {
    int gid  = blockIdx.x * blockDim.x + threadIdx.x;
    int lane = threadIdx.x & 31;

    // --- row_ptr ---
    {
        int ee = min(gid, E - 1);
        int r  = rows[ee];
        int rp = 0;
        if (lane == 0 && ee > 0) rp = rows[ee - 1];
        int rs = __shfl_up_sync(0xffffffff, r, 1);
        if (lane > 0) rp = rs;
        if (gid < E) {
            if (gid == 0) rp = -1;
            for (int j = rp + 1; j <= r; j++) g_row_ptr[j] = gid;
            if (gid == E - 1)
                for (int j = r + 1; j <= N_NODES; j++) g_row_ptr[j] = E;
        }
    }

    // --- h -> fp16 (one float4 per thread) ---
    const int total = (N_NODES * D) / 4;
    if (gid < total) {
        float4 f = __ldg(((const float4*)h) + gid);
        __half2 a = __floats2half2_rn(f.x, f.y);
        __half2 b = __floats2half2_rn(f.z, f.w);
        uint2 packed;
        packed.x = *(unsigned int*)&a;
        packed.y = *(unsigned int*)&b;
        ((uint2*)g_h16)[gid] = packed;
    }
}

// ---------------------------------------------------------------------------
// Kernel 2: SpMM on fp16 h — one warp per node (R4 shape: best measured).
// ---------------------------------------------------------------------------
__global__ void __launch_bounds__(256) spmm_kernel(const int*   __restrict__ cols,
                                                   const float* __restrict__ vals) {
    int gwarp = (blockIdx.x * blockDim.x + threadIdx.x) >> 5;
    int lane  = threadIdx.x & 31;
    if (gwarp >= N_NODES) return;

    int s = g_row_ptr[gwarp];
    int e = g_row_ptr[gwarp + 1];

    float4 acc = make_float4(0.f, 0.f, 0.f, 0.f);

    for (int base = s; base < e; base += 32) {
        int   idx = base + lane;
        int   c   = 0;
        float v   = 0.f;
        if (idx < e) {
            c = __ldg(&cols[idx]);
            v = __ldg(&vals[idx]);
        }
        int cnt = min(32, e - base);
        #pragma unroll 4
        for (int j = 0; j < cnt; j++) {
            int   cc = __shfl_sync(0xffffffff, c, j);
            float vv = __shfl_sync(0xffffffff, v, j);
            uint2 hv = __ldg((const uint2*)(g_h16 + (size_t)cc * D) + lane);
            float2 f0 = __half22float2(*(__half2*)&hv.x);
            float2 f1 = __half22float2(*(__half2*)&hv.y);
            acc.x += vv * f0.x;
            acc.y += vv * f0.y;
            acc.z += vv * f1.x;
            acc.w += vv * f1.y;
        }
    }
    ((float4*)(g_agg + (size_t)gwarp * D))[lane] = acc;
}

// ---------------------------------------------------------------------------
// Kernel 3: out = relu(agg @ W^T + b) via tf32 mma.sync (m16n8k8).
// 256 threads (8 warps: 4 m-warps x 2 n-warps). Block tile 128x128, K=128.
// Fragments pre-permuted in smem so mainloop loads are contiguous LDS.64.
//
// Fragment layouts (per PTX m16n8k8):
//   A:  a0=(r,c) a1=(r+8,c) a2=(r,c+4) a3=(r+8,c+4),  r=lane/4, c=lane%4
//   B:  b0=(k=c, n=lane/4)  b1=(k=c+4, n=lane/4)      (col-major B)
//   D:  c0=(r,2c) c1=(r,2c+1) c2=(r+8,2c) c3=(r+8,2c+1)
// ---------------------------------------------------------------------------
__global__ void __launch_bounds__(256, 1) gemm_bias_relu_kernel(const float* __restrict__ W,
                                                                const float* __restrict__ b,
                                                                float* __restrict__ out) {
    extern __shared__ float sm[];
    float* As = sm;            // [i(8)][t(16)][p(2)][l(32)][e(2)] = 16384 floats
    float* Ws = sm + 16384;    // [j(16)][t(16)][l(32)][e(2)]     = 16384 floats

    const int tid   = threadIdx.x;
    const int lane  = tid & 31;
    const int warp  = tid >> 5;
    const int wm    = warp >> 1;    // 0..3  (32 rows each)
    const int wn    = warp & 1;     // 0..1  (64 cols each)
    const int node0 = blockIdx.x * MTG;

    // ---- Fill A fragments from g_agg (coalesced float4 reads, tf32 cvt) ----
    for (int idx = tid; idx < MTG * (D / 4); idx += 256) {
        int row = idx >> 5;            // 0..127
        int q   = idx & 31;            // float4 index within row
        int gn  = node0 + row;
        float4 f = (gn < N_NODES)
                 ? __ldg((const float4*)(g_agg + (size_t)gn * D) + q)
                 : make_float4(0.f, 0.f, 0.f, 0.f);
        int t = q >> 1, e = q & 1;
        int i = row >> 4, p = (row >> 3) & 1;
        int lb = (row & 7) * 4;
        float* base = As + ((((i * 16 + t) * 2 + p) * 32 + lb) * 2 + e);
        base[0] = __uint_as_float(f2tf32(f.x));
        base[2] = __uint_as_float(f2tf32(f.y));
        base[4] = __uint_as_float(f2tf32(f.z));
        base[6] = __uint_as_float(f2tf32(f.w));
    }
    // ---- Fill B fragments from W (row-major [n][k]) ----
    for (int idx = tid; idx < D * (D / 4); idx += 256) {
        int n = idx >> 5;
        int q = idx & 31;
        float4 f = __ldg((const float4*)(W + (size_t)n * D) + q);
        int t = q >> 1, e = q & 1;
        int j = n >> 3;
        int lb = (n & 7) * 4;
        float* base = Ws + (((j * 16 + t) * 32 + lb) * 2 + e);
        base[0] = __uint_as_float(f2tf32(f.x));
        base[2] = __uint_as_float(f2tf32(f.y));
        base[4] = __uint_as_float(f2tf32(f.z));
        base[6] = __uint_as_float(f2tf32(f.w));
    }
    __syncthreads();

    float acc[2][8][4];
    #pragma unroll
    for (int i2 = 0; i2 < 2; i2++)
        #pragma unroll
        for (int j2 = 0; j2 < 8; j2++)
            #pragma unroll
            for (int x = 0; x < 4; x++)
                acc[i2][j2][x] = 0.f;

    #pragma unroll
    for (int t = 0; t < 16; t++) {
        uint32_t a0[2], a1[2], a2[2], a3[2];
        #pragma unroll
        for (int i2 = 0; i2 < 2; i2++) {
            int i = wm * 2 + i2;
            const float* ab = As + ((((i * 16 + t) * 2 + 0) * 32 + lane) * 2);
            u64 v0 = *(const u64*)ab;         // p=0: (a0, a2)
            u64 v1 = *(const u64*)(ab + 64);  // p=1: (a1, a3)
            unpack_u64(v0, a0[i2], a2[i2]);
            unpack_u64(v1, a1[i2], a3[i2]);
        }
        #pragma unroll
        for (int j2 = 0; j2 < 8; j2++) {
            int j = wn * 8 + j2;
            u64 bv = *(const u64*)(Ws + (((j * 16 + t) * 32 + lane) * 2));
            uint32_t b0, b1;
            unpack_u64(bv, b0, b1);
            #pragma unroll
            for (int i2 = 0; i2 < 2; i2++)
                mma_tf32(acc[i2][j2], a0[i2], a1[i2], a2[i2], a3[i2], b0, b1);
        }
    }

    // ---- Epilogue: + bias, relu, float2 stores (full 32B sectors) ----
    const int r    = lane >> 2;
    const int c2   = (lane & 3) * 2;
    float2 bias[8];
    #pragma unroll
    for (int j2 = 0; j2 < 8; j2++) {
        int col = wn * 64 + j2 * 8 + c2;
        bias[j2] = *(const float2*)(b + col);
    }

    #pragma unroll
    for (int i2 = 0; i2 < 2; i2++) {
        int row0 = node0 + wm * 32 + i2 * 16 + r;
        #pragma unroll
        for (int j2 = 0; j2 < 8; j2++) {
            int col = wn * 64 + j2 * 8 + c2;
            if (row0 < N_NODES) {
                float2 o;
                o.x = fmaxf(acc[i2][j2][0] + bias[j2].x, 0.f);
                o.y = fmaxf(acc[i2][j2][1] + bias[j2].y, 0.f);
                *(float2*)(out + (size_t)row0 * D + col) = o;
            }
            if (row0 + 8 < N_NODES) {
                float2 o;
                o.x = fmaxf(acc[i2][j2][2] + bias[j2].x, 0.f);
                o.y = fmaxf(acc[i2][j2][3] + bias[j2].y, 0.f);
                *(float2*)(out + (size_t)(row0 + 8) * D + col) = o;
            }
        }
    }
}

// ---------------------------------------------------------------------------
// Launch
// ---------------------------------------------------------------------------
extern "C" void kernel_launch(void* const* d_in, const int* in_sizes, int n_in,
                              void* d_out, int out_size) {
    const int*   edge_rows = (const int*)  d_in[0];
    const int*   edge_cols = (const int*)  d_in[1];
    const float* edge_vals = (const float*)d_in[2];
    const float* h         = (const float*)d_in[3];
    const float* W         = (const float*)d_in[4];
    const float* b         = (const float*)d_in[5];
    float*       out       = (float*)d_out;
    const int E = in_sizes[0];

    // 1) prep: row_ptr + h->fp16 in one launch
    {
        int work   = max(E, (N_NODES * D) / 4);
        int blocks = (work + 255) / 256;
        prep_kernel<<<blocks, 256>>>(edge_rows, E, h);
    }

    // 2) SpMM (fp16 gather, fp32 accumulate)
    {
        long long total_threads = (long long)N_NODES * 32;
        int blocks = (int)((total_threads + 255) / 256);
        spmm_kernel<<<blocks, 256>>>(edge_cols, edge_vals);
    }

    // 3) GEMM + bias + relu (tf32 tensor cores)
    cudaFuncSetAttribute(gemm_bias_relu_kernel,
                         cudaFuncAttributeMaxDynamicSharedMemorySize,
                         GEMM_SMEM_BYTES);
    gemm_bias_relu_kernel<<<(N_NODES + MTG - 1) / MTG, 256, GEMM_SMEM_BYTES>>>(W, b, out);
}

// round 7
// speedup vs baseline: 1.5244x; 1.4269x over previous
#include <cuda_runtime.h>
#include <cuda_fp16.h>
#include <cstdint>

#define N_NODES 100000
#define D 128
#define MTG 128                                   // rows per GEMM block
#define GEMM_SMEM_BYTES ((8192 + 8192) * 4)       // As + Bs fragments, 64KB

typedef unsigned long long u64;

// Scratch (allocation-free rule: __device__ globals)
__device__ int            g_row_ptr[N_NODES + 1];
__device__ unsigned short g_hp16[(size_t)N_NODES * D];   // h' = h @ W^T, fp16

// ---------------------------------------------------------------------------
// helpers
// ---------------------------------------------------------------------------
__device__ __forceinline__ uint32_t packh2(float x, float y) {
    __half2 h = __floats2half2_rn(x, y);
    return *(uint32_t*)&h;
}
__device__ __forceinline__ void unpack_u64(u64 v, uint32_t& lo, uint32_t& hi) {
    asm("mov.b64 {%0, %1}, %2;" : "=r"(lo), "=r"(hi) : "l"(v));
}
__device__ __forceinline__ void mma_f16(float d[4],
                                        uint32_t a0, uint32_t a1, uint32_t a2, uint32_t a3,
                                        uint32_t b0, uint32_t b1) {
    asm volatile(
        "mma.sync.aligned.m16n8k16.row.col.f32.f16.f16.f32 "
        "{%0,%1,%2,%3}, {%4,%5,%6,%7}, {%8,%9}, {%0,%1,%2,%3};"
        : "+f"(d[0]), "+f"(d[1]), "+f"(d[2]), "+f"(d[3])
        : "r"(a0), "r"(a1), "r"(a2), "r"(a3), "r"(b0), "r"(b1));
}

// ---------------------------------------------------------------------------
// Kernel 1: CSR row pointers from sorted edge_rows (shfl neighbor)
// ---------------------------------------------------------------------------
__global__ void __launch_bounds__(256) build_row_ptr_kernel(const int* __restrict__ rows, int E) {
    int e    = blockIdx.x * blockDim.x + threadIdx.x;
    int lane = threadIdx.x & 31;
    int ee   = min(e, E - 1);
    int r    = rows[ee];
    int rp   = 0;
    if (lane == 0 && ee > 0) rp = rows[ee - 1];
    int rs = __shfl_up_sync(0xffffffff, r, 1);
    if (lane > 0) rp = rs;
    if (e >= E) return;
    if (e == 0) rp = -1;
    for (int j = rp + 1; j <= r; j++) g_row_ptr[j] = e;
    if (e == E - 1)
        for (int j = r + 1; j <= N_NODES; j++) g_row_ptr[j] = E;
}

// ---------------------------------------------------------------------------
// Kernel 2: h' = h @ W^T via fp16 mma.m16n8k16, h'[row][j] stored fp16.
// 256 threads = 8 warps (wm 0..3 x wn 0..1); block tile 128x128, K=128.
// Fragment smem layout (u32 = packed half2 of 2 consecutive k):
//   As[i(8 m16)][t(8 k16)][pr(2)][slot(32)][pk(2)]  -> word (i*8+t)*128 + pr*64 + slot*2 + pk
//   Bs[j(16 n8)][t(8)]       [slot(32)][pk(2)]      -> word (j*8+t)*64  + slot*2 + pk
// slot = (row%8)*4 + pair%4, pk = pair/4  (pair = k16-local column pair 0..7)
// Mainloop: LDS.64 per (pr) / per (j) — lane-consecutive, conflict-free.
// ---------------------------------------------------------------------------
__global__ void __launch_bounds__(256, 1) gemm_h_kernel(const float* __restrict__ h,
                                                        const float* __restrict__ W) {
    extern __shared__ uint32_t smu[];
    uint32_t* As = smu;          // 8192 u32
    uint32_t* Bs = smu + 8192;   // 8192 u32

    const int tid   = threadIdx.x;
    const int lane  = tid & 31;
    const int warp  = tid >> 5;
    const int wm    = warp >> 1;     // 0..3 (32 rows)
    const int wn    = warp & 1;      // 0..1 (64 cols)
    const int node0 = blockIdx.x * MTG;

    // ---- Fill A fragments from h (fp32 -> fp16), coalesced float4 reads ----
    for (int idx = tid; idx < MTG * (D / 4); idx += 256) {
        int row = idx >> 5, q = idx & 31;
        int gn  = node0 + row;
        float4 f = (gn < N_NODES)
                 ? __ldg((const float4*)(h + (size_t)gn * D) + q)
                 : make_float4(0.f, 0.f, 0.f, 0.f);
        int t = q >> 2, q4 = q & 3;
        int pk = q4 >> 1, e = q4 & 1;
        int i = row >> 4, pr = (row >> 3) & 1, r8 = row & 7;
        int slot0 = r8 * 4 + 2 * e;
        uint32_t* base = As + (i * 8 + t) * 128 + pr * 64;
        base[slot0 * 2 + pk]       = packh2(f.x, f.y);   // pair 2*q4
        base[(slot0 + 1) * 2 + pk] = packh2(f.z, f.w);   // pair 2*q4+1
    }
    // ---- Fill B fragments from W ([n][k] row-major == col-major B) ----
    for (int idx = tid; idx < D * (D / 4); idx += 256) {
        int n = idx >> 5, q = idx & 31;
        float4 f = __ldg((const float4*)(W + (size_t)n * D) + q);
        int t = q >> 2, q4 = q & 3;
        int pk = q4 >> 1, e = q4 & 1;
        int j = n >> 3, r8 = n & 7;
        int slot0 = r8 * 4 + 2 * e;
        uint32_t* base = Bs + (j * 8 + t) * 64;
        base[slot0 * 2 + pk]       = packh2(f.x, f.y);
        base[(slot0 + 1) * 2 + pk] = packh2(f.z, f.w);
    }
    __syncthreads();

    float acc[2][8][4];
    #pragma unroll
    for (int i2 = 0; i2 < 2; i2++)
        #pragma unroll
        for (int j2 = 0; j2 < 8; j2++)
            #pragma unroll
            for (int x = 0; x < 4; x++)
                acc[i2][j2][x] = 0.f;

    #pragma unroll
    for (int t = 0; t < 8; t++) {
        uint32_t a[2][4];
        #pragma unroll
        for (int i2 = 0; i2 < 2; i2++) {
            const uint32_t* ab = As + ((wm * 2 + i2) * 8 + t) * 128;
            u64 v0 = *(const u64*)(ab + lane * 2);        // pr=0: (a0, a2)
            u64 v1 = *(const u64*)(ab + 64 + lane * 2);   // pr=1: (a1, a3)
            unpack_u64(v0, a[i2][0], a[i2][2]);
            unpack_u64(v1, a[i2][1], a[i2][3]);
        }
        #pragma unroll
        for (int j2 = 0; j2 < 8; j2++) {
            u64 bv = *(const u64*)(Bs + ((wn * 8 + j2) * 8 + t) * 64 + lane * 2);
            uint32_t b0, b1;
            unpack_u64(bv, b0, b1);
            #pragma unroll
            for (int i2 = 0; i2 < 2; i2++)
                mma_f16(acc[i2][j2], a[i2][0], a[i2][1], a[i2][2], a[i2][3], b0, b1);
        }
    }

    // ---- Epilogue: store h' as fp16 (packed half2 per c-pair) ----
    const int r  = lane >> 2;
    const int c2 = (lane & 3) * 2;
    #pragma unroll
    for (int i2 = 0; i2 < 2; i2++) {
        int row0 = node0 + wm * 32 + i2 * 16 + r;
        #pragma unroll
        for (int j2 = 0; j2 < 8; j2++) {
            int col = wn * 64 + j2 * 8 + c2;
            if (row0 < N_NODES)
                *(uint32_t*)(g_hp16 + (size_t)row0 * D + col) =
                    packh2(acc[i2][j2][0], acc[i2][j2][1]);
            if (row0 + 8 < N_NODES)
                *(uint32_t*)(g_hp16 + (size_t)(row0 + 8) * D + col) =
                    packh2(acc[i2][j2][2], acc[i2][j2][3]);
        }
    }
}

// ---------------------------------------------------------------------------
// Kernel 3: fused SpMM + bias + relu on h'16 — one warp per node (R4 shape).
// out[i] = relu( sum_e v_e * h'[col_e] + b )
// ---------------------------------------------------------------------------
__global__ void __launch_bounds__(256) spmm_kernel(const int*   __restrict__ cols,
                                                   const float* __restrict__ vals,
                                                   const float* __restrict__ b,
                                                   float*       __restrict__ out) {
    int gwarp = (blockIdx.x * blockDim.x + threadIdx.x) >> 5;
    int lane  = threadIdx.x & 31;
    if (gwarp >= N_NODES) return;

    int s = g_row_ptr[gwarp];
    int e = g_row_ptr[gwarp + 1];

    float4 acc = make_float4(0.f, 0.f, 0.f, 0.f);

    for (int base = s; base < e; base += 32) {
        int   idx = base + lane;
        int   c   = 0;
        float v   = 0.f;
        if (idx < e) {
            c = __ldg(&cols[idx]);
            v = __ldg(&vals[idx]);
        }
        int cnt = min(32, e - base);
        #pragma unroll 4
        for (int j = 0; j < cnt; j++) {
            int   cc = __shfl_sync(0xffffffff, c, j);
            float vv = __shfl_sync(0xffffffff, v, j);
            uint2 hv = __ldg((const uint2*)(g_hp16 + (size_t)cc * D) + lane);
            float2 f0 = __half22float2(*(__half2*)&hv.x);
            float2 f1 = __half22float2(*(__half2*)&hv.y);
            acc.x += vv * f0.x;
            acc.y += vv * f0.y;
            acc.z += vv * f1.x;
            acc.w += vv * f1.y;
        }
    }

    float4 bb = __ldg((const float4*)b + lane);
    float4 o;
    o.x = fmaxf(acc.x + bb.x, 0.f);
    o.y = fmaxf(acc.y + bb.y, 0.f);
    o.z = fmaxf(acc.z + bb.z, 0.f);
    o.w = fmaxf(acc.w + bb.w, 0.f);
    ((float4*)(out + (size_t)gwarp * D))[lane] = o;
}

// ---------------------------------------------------------------------------
// Launch
// ---------------------------------------------------------------------------
extern "C" void kernel_launch(void* const* d_in, const int* in_sizes, int n_in,
                              void* d_out, int out_size) {
    const int*   edge_rows = (const int*)  d_in[0];
    const int*   edge_cols = (const int*)  d_in[1];
    const float* edge_vals = (const float*)d_in[2];
    const float* h         = (const float*)d_in[3];
    const float* W         = (const float*)d_in[4];
    const float* b         = (const float*)d_in[5];
    float*       out       = (float*)d_out;
    const int E = in_sizes[0];

    // 1) CSR row pointers
    build_row_ptr_kernel<<<(E + 255) / 256, 256>>>(edge_rows, E);

    // 2) h' = h @ W^T (fp16 tensor cores, fp32 accumulate, fp16 store)
    cudaFuncSetAttribute(gemm_h_kernel,
                         cudaFuncAttributeMaxDynamicSharedMemorySize,
                         GEMM_SMEM_BYTES);
    gemm_h_kernel<<<(N_NODES + MTG - 1) / MTG, 256, GEMM_SMEM_BYTES>>>(h, W);

    // 3) fused SpMM + bias + relu -> out
    {
        long long total_threads = (long long)N_NODES * 32;
        int blocks = (int)((total_threads + 255) / 256);
        spmm_kernel<<<blocks, 256>>>(edge_cols, edge_vals, b, out);
    }
}

// round 8
// speedup vs baseline: 1.5313x; 1.0046x over previous
#include <cuda_runtime.h>
#include <cuda_fp16.h>
#include <cstdint>

#define N_NODES 100000
#define D 128
#define MTG 128                                   // rows per GEMM block
#define GEMM_SMEM_BYTES ((8192 + 8192) * 4)       // As + Bs fragments, 64KB

typedef unsigned long long u64;

// Scratch (allocation-free rule: __device__ globals)
__device__ int            g_row_ptr[N_NODES + 1];
__device__ unsigned short g_hp16[(size_t)N_NODES * D];   // h' = h @ W^T, fp16

// ---------------------------------------------------------------------------
// helpers
// ---------------------------------------------------------------------------
__device__ __forceinline__ uint32_t packh2(float x, float y) {
    __half2 h = __floats2half2_rn(x, y);
    return *(uint32_t*)&h;
}
__device__ __forceinline__ void unpack_u64(u64 v, uint32_t& lo, uint32_t& hi) {
    asm("mov.b64 {%0, %1}, %2;" : "=r"(lo), "=r"(hi) : "l"(v));
}
__device__ __forceinline__ void mma_f16(float d[4],
                                        uint32_t a0, uint32_t a1, uint32_t a2, uint32_t a3,
                                        uint32_t b0, uint32_t b1) {
    asm volatile(
        "mma.sync.aligned.m16n8k16.row.col.f32.f16.f16.f32 "
        "{%0,%1,%2,%3}, {%4,%5,%6,%7}, {%8,%9}, {%0,%1,%2,%3};"
        : "+f"(d[0]), "+f"(d[1]), "+f"(d[2]), "+f"(d[3])
        : "r"(a0), "r"(a1), "r"(a2), "r"(a3), "r"(b0), "r"(b1));
}
__device__ __forceinline__ u64 pack2f(float x, float y) {
    u64 r; asm("mov.b64 %0, {%1, %2};" : "=l"(r) : "f"(x), "f"(y)); return r;
}
__device__ __forceinline__ u64 fma2(u64 a, u64 b, u64 c) {
    u64 d; asm("fma.rn.f32x2 %0, %1, %2, %3;" : "=l"(d) : "l"(a), "l"(b), "l"(c));
    return d;
}
__device__ __forceinline__ float2 unpack2f(u64 v) {
    float2 f; asm("mov.b64 {%0, %1}, %2;" : "=f"(f.x), "=f"(f.y) : "l"(v)); return f;
}

// ---------------------------------------------------------------------------
// Kernel 1: h' = h @ W^T via fp16 mma.m16n8k16 (fragments pre-permuted in smem)
// + fused CSR row-pointer build appended at the tail (overlaps across waves).
// ---------------------------------------------------------------------------
__global__ void __launch_bounds__(256, 1) gemm_h_kernel(const float* __restrict__ h,
                                                        const float* __restrict__ W,
                                                        const int*   __restrict__ rows,
                                                        int E, int nblocks) {
    extern __shared__ uint32_t smu[];
    uint32_t* As = smu;          // 8192 u32
    uint32_t* Bs = smu + 8192;   // 8192 u32

    const int tid   = threadIdx.x;
    const int lane  = tid & 31;
    const int warp  = tid >> 5;
    const int wm    = warp >> 1;     // 0..3 (32 rows)
    const int wn    = warp & 1;      // 0..1 (64 cols)
    const int node0 = blockIdx.x * MTG;

    // ---- Fill A fragments from h (fp32 -> fp16), coalesced float4 reads ----
    for (int idx = tid; idx < MTG * (D / 4); idx += 256) {
        int row = idx >> 5, q = idx & 31;
        int gn  = node0 + row;
        float4 f = (gn < N_NODES)
                 ? __ldg((const float4*)(h + (size_t)gn * D) + q)
                 : make_float4(0.f, 0.f, 0.f, 0.f);
        int t = q >> 2, q4 = q & 3;
        int pk = q4 >> 1, e = q4 & 1;
        int i = row >> 4, pr = (row >> 3) & 1, r8 = row & 7;
        int slot0 = r8 * 4 + 2 * e;
        uint32_t* base = As + (i * 8 + t) * 128 + pr * 64;
        base[slot0 * 2 + pk]       = packh2(f.x, f.y);
        base[(slot0 + 1) * 2 + pk] = packh2(f.z, f.w);
    }
    // ---- Fill B fragments from W ([n][k] row-major == col-major B) ----
    for (int idx = tid; idx < D * (D / 4); idx += 256) {
        int n = idx >> 5, q = idx & 31;
        float4 f = __ldg((const float4*)(W + (size_t)n * D) + q);
        int t = q >> 2, q4 = q & 3;
        int pk = q4 >> 1, e = q4 & 1;
        int j = n >> 3, r8 = n & 7;
        int slot0 = r8 * 4 + 2 * e;
        uint32_t* base = Bs + (j * 8 + t) * 64;
        base[slot0 * 2 + pk]       = packh2(f.x, f.y);
        base[(slot0 + 1) * 2 + pk] = packh2(f.z, f.w);
    }
    __syncthreads();

    float acc[2][8][4];
    #pragma unroll
    for (int i2 = 0; i2 < 2; i2++)
        #pragma unroll
        for (int j2 = 0; j2 < 8; j2++)
            #pragma unroll
            for (int x = 0; x < 4; x++)
                acc[i2][j2][x] = 0.f;

    #pragma unroll
    for (int t = 0; t < 8; t++) {
        uint32_t a[2][4];
        #pragma unroll
        for (int i2 = 0; i2 < 2; i2++) {
            const uint32_t* ab = As + ((wm * 2 + i2) * 8 + t) * 128;
            u64 v0 = *(const u64*)(ab + lane * 2);        // pr=0: (a0, a2)
            u64 v1 = *(const u64*)(ab + 64 + lane * 2);   // pr=1: (a1, a3)
            unpack_u64(v0, a[i2][0], a[i2][2]);
            unpack_u64(v1, a[i2][1], a[i2][3]);
        }
        #pragma unroll
        for (int j2 = 0; j2 < 8; j2++) {
            u64 bv = *(const u64*)(Bs + ((wn * 8 + j2) * 8 + t) * 64 + lane * 2);
            uint32_t b0, b1;
            unpack_u64(bv, b0, b1);
            #pragma unroll
            for (int i2 = 0; i2 < 2; i2++)
                mma_f16(acc[i2][j2], a[i2][0], a[i2][1], a[i2][2], a[i2][3], b0, b1);
        }
    }

    // ---- Epilogue: store h' as fp16 (packed half2 per c-pair) ----
    const int r  = lane >> 2;
    const int c2 = (lane & 3) * 2;
    #pragma unroll
    for (int i2 = 0; i2 < 2; i2++) {
        int row0 = node0 + wm * 32 + i2 * 16 + r;
        #pragma unroll
        for (int j2 = 0; j2 < 8; j2++) {
            int col = wn * 64 + j2 * 8 + c2;
            if (row0 < N_NODES)
                *(uint32_t*)(g_hp16 + (size_t)row0 * D + col) =
                    packh2(acc[i2][j2][0], acc[i2][j2][1]);
            if (row0 + 8 < N_NODES)
                *(uint32_t*)(g_hp16 + (size_t)(row0 + 8) * D + col) =
                    packh2(acc[i2][j2][2], acc[i2][j2][3]);
        }
    }

    // ---- Fused row_ptr build: each thread owns a contiguous 16-edge chunk ----
    {
        int gtid  = blockIdx.x * 256 + tid;
        int total = nblocks * 256;
        int chunk = (E + total - 1) / total;           // edges per thread
        chunk = (chunk + 15) & ~15;                    // keep int4 alignment
        int base  = gtid * chunk;
        if (base < E) {
            int prev = (base == 0) ? -1 : __ldg(&rows[base - 1]);
            for (int i0 = 0; i0 < chunk; i0 += 4) {
                int e0 = base + i0;
                if (e0 >= E) break;
                int4 r4;
                if (e0 + 4 <= E) {
                    r4 = __ldg((const int4*)(rows + e0));
                } else {
                    r4.x = __ldg(&rows[e0]);
                    r4.y = (e0 + 1 < E) ? __ldg(&rows[e0 + 1]) : r4.x;
                    r4.z = (e0 + 2 < E) ? __ldg(&rows[e0 + 2]) : r4.y;
                    r4.w = (e0 + 3 < E) ? __ldg(&rows[e0 + 3]) : r4.z;
                }
                const int rr[4] = {r4.x, r4.y, r4.z, r4.w};
                #pragma unroll
                for (int q = 0; q < 4; q++) {
                    int e = e0 + q;
                    if (e >= E) break;
                    int rv = rr[q];
                    for (int j = prev + 1; j <= rv; j++) g_row_ptr[j] = e;
                    prev = rv;
                    if (e == E - 1)
                        for (int j = rv + 1; j <= N_NODES; j++) g_row_ptr[j] = E;
                }
            }
        }
    }
}

// ---------------------------------------------------------------------------
// Kernel 2: fused SpMM + bias + relu on h'16 — one warp per node.
// f32x2 packed accumulate (2 fma2 per edge instead of 4 FFMA).
// ---------------------------------------------------------------------------
__global__ void __launch_bounds__(256) spmm_kernel(const int*   __restrict__ cols,
                                                   const float* __restrict__ vals,
                                                   const float* __restrict__ b,
                                                   float*       __restrict__ out) {
    int gwarp = (blockIdx.x * blockDim.x + threadIdx.x) >> 5;
    int lane  = threadIdx.x & 31;
    if (gwarp >= N_NODES) return;

    int s = g_row_ptr[gwarp];
    int e = g_row_ptr[gwarp + 1];

    u64 acc0 = pack2f(0.f, 0.f);
    u64 acc1 = pack2f(0.f, 0.f);

    for (int base = s; base < e; base += 32) {
        int   idx = base + lane;
        int   c   = 0;
        float v   = 0.f;
        if (idx < e) {
            c = __ldg(&cols[idx]);
            v = __ldg(&vals[idx]);
        }
        int cnt = min(32, e - base);
        #pragma unroll 4
        for (int j = 0; j < cnt; j++) {
            int   cc = __shfl_sync(0xffffffff, c, j);
            float vv = __shfl_sync(0xffffffff, v, j);
            u64   v2 = pack2f(vv, vv);
            uint2 hv = __ldg((const uint2*)(g_hp16 + (size_t)cc * D) + lane);
            float2 f0 = __half22float2(*(__half2*)&hv.x);
            float2 f1 = __half22float2(*(__half2*)&hv.y);
            acc0 = fma2(v2, pack2f(f0.x, f0.y), acc0);
            acc1 = fma2(v2, pack2f(f1.x, f1.y), acc1);
        }
    }

    float2 p0 = unpack2f(acc0);
    float2 p1 = unpack2f(acc1);
    float4 bb = __ldg((const float4*)b + lane);
    float4 o;
    o.x = fmaxf(p0.x + bb.x, 0.f);
    o.y = fmaxf(p0.y + bb.y, 0.f);
    o.z = fmaxf(p1.x + bb.z, 0.f);
    o.w = fmaxf(p1.y + bb.w, 0.f);
    ((float4*)(out + (size_t)gwarp * D))[lane] = o;
}

// ---------------------------------------------------------------------------
// Launch
// ---------------------------------------------------------------------------
extern "C" void kernel_launch(void* const* d_in, const int* in_sizes, int n_in,
                              void* d_out, int out_size) {
    const int*   edge_rows = (const int*)  d_in[0];
    const int*   edge_cols = (const int*)  d_in[1];
    const float* edge_vals = (const float*)d_in[2];
    const float* h         = (const float*)d_in[3];
    const float* W         = (const float*)d_in[4];
    const float* b         = (const float*)d_in[5];
    float*       out       = (float*)d_out;
    const int E = in_sizes[0];

    // 1) h' = h @ W^T (fp16 tensor cores) + fused row_ptr build
    const int nblocks = (N_NODES + MTG - 1) / MTG;
    cudaFuncSetAttribute(gemm_h_kernel,
                         cudaFuncAttributeMaxDynamicSharedMemorySize,
                         GEMM_SMEM_BYTES);
    gemm_h_kernel<<<nblocks, 256, GEMM_SMEM_BYTES>>>(h, W, edge_rows, E, nblocks);

    // 2) fused SpMM + bias + relu -> out
    {
        long long total_threads = (long long)N_NODES * 32;
        int blocks = (int)((total_threads + 255) / 256);
        spmm_kernel<<<blocks, 256>>>(edge_cols, edge_vals, b, out);
    }
}